// round 14
// baseline (speedup 1.0000x reference)
#include <cuda_runtime.h>
#include <cuda_fp8.h>
#include <cstdint>
#include <cstddef>

#define MM 16384
#define KK 4096
#define NN 4096
#define KTILES (KK/128)   // 32
#define NTILES (NN/128)   // 32
#define MTILES (MM/128)   // 128
#define TILE_BYTES 16384
#define STAGES 4
#define STAGE_BYTES (2*TILE_BYTES)            // A(16KB) + B(16KB)
#define SMEM_DYN (1024 + STAGES*STAGE_BYTES)  // 132 KB
#define NTG 288           // 8 compute warps (64x32 tiles) + 1 producer warp

// Evidence log: plain compute_103 device pass (R2) -> mma.sync fp8 path runs.
// R6 (8 warps x 64x32, ~130 regs, NO spill): total 406us, GEMM ~260us — best.
// R7/R8/R10/R13: every 64x64-accum tile spilled (regs pinned at 255 cap,
// L1 17-72%) -> shape abandoned. LDSM traffic depends only on warp-tile size,
// so all no-spill tiles equal R6's traffic. This round: R6 GEMM verbatim
// (+1 pipeline stage), phases consolidated to 3 launches, and FINALLY profile
// the R6-shape gemm to decide QMMA-floor vs LDSM-bound.

// ---------------- scratch (device globals: allocation-free) ----------------
__device__ __align__(1024) unsigned char g_xq[(size_t)MM*KK]; // 64 MB, tiled+swizzled
__device__ __align__(1024) unsigned char g_wq[(size_t)NN*KK]; // 16 MB, tiled+swizzled
__device__ unsigned g_absmax[2];  // zero-init; atomicMax idempotent across replays

// ---------------- PTX helpers ----------------
__device__ __forceinline__ uint32_t smem_u32(const void* p) {
    uint32_t a;
    asm("{ .reg .u64 t; cvta.to.shared.u64 t, %1; cvt.u32.u64 %0, t; }" : "=r"(a) : "l"(p));
    return a;
}
__device__ __forceinline__ uint32_t elect_one_pred() {
    uint32_t p;
    asm volatile("{ .reg .pred p; elect.sync _|p, 0xFFFFFFFF; selp.b32 %0, 1, 0, p; }" : "=r"(p));
    return p;
}
#define MBARRIER_INIT(addr, cnt) \
    asm volatile("mbarrier.init.shared.b64 [%0], %1;" :: "r"(addr), "r"(cnt) : "memory")
#define MBARRIER_EXPECT_TX(addr, bytes) \
    asm volatile("mbarrier.arrive.expect_tx.shared.b64 _, [%0], %1;" :: "r"(addr), "r"(bytes) : "memory")
#define MBARRIER_ARRIVE(addr) \
    asm volatile("mbarrier.arrive.shared.b64 _, [%0];" :: "r"(addr) : "memory")
#define MBARRIER_WAIT_PARITY(mbar_smem_addr, phase_parity) do { \
    uint32_t _mbar = (uint32_t)(mbar_smem_addr); \
    uint32_t _parity = (uint32_t)(phase_parity); \
    uint32_t _done; \
    asm volatile("{ .reg .pred p; mbarrier.try_wait.parity.acquire.cta.shared::cta.b64 p, [%1], %2; selp.b32 %0, 1, 0, p; }" \
        : "=r"(_done) : "r"(_mbar), "r"(_parity) : "memory"); \
    if (!_done) { \
        asm volatile("{ .reg .pred P1; WAIT_LOOP_%=: mbarrier.try_wait.parity.acquire.cta.shared::cta.b64 P1, [%0], %1, 0x989680; @P1 bra.uni WAIT_DONE_%=; bra.uni WAIT_LOOP_%=; WAIT_DONE_%=: }" \
            :: "r"(_mbar), "r"(_parity) : "memory"); \
    } \
} while(0)
#define MBARRIER_WAIT_PARITY_RELAXED(mbar_smem_addr, phase_parity) do { \
    uint32_t _mbar = (uint32_t)(mbar_smem_addr); \
    uint32_t _parity = (uint32_t)(phase_parity); \
    uint32_t _done; \
    asm volatile("{ .reg .pred p; mbarrier.try_wait.parity.relaxed.cta.shared::cta.b64 p, [%1], %2, 0x989680; selp.b32 %0, 1, 0, p; }" \
        : "=r"(_done) : "r"(_mbar), "r"(_parity) : "memory"); \
    if (!_done) { \
        asm volatile("{ .reg .pred P1; WAIT_LOOP_%=: mbarrier.try_wait.parity.relaxed.cta.shared::cta.b64 P1, [%0], %1, 0x989680; @P1 bra.uni WAIT_DONE_%=; bra.uni WAIT_LOOP_%=; WAIT_DONE_%=: }" \
            :: "r"(_mbar), "r"(_parity) : "memory"); \
    } \
} while(0)

__device__ __forceinline__ void bulk_g2s(uint32_t dst, const void* src, uint32_t bytes, uint32_t mbar) {
    asm volatile(
        "cp.async.bulk.shared::cluster.global.mbarrier::complete_tx::bytes [%0], [%1], %2, [%3];"
        :: "r"(dst), "l"(src), "r"(bytes), "r"(mbar) : "memory");
}

__device__ __forceinline__ unsigned swz128(unsigned off) { return off ^ ((off >> 3) & 0x70); }
__device__ __forceinline__ unsigned char q_e4m3(float v) {
    return (unsigned char)__nv_cvt_float_to_fp8(v, __NV_SATFINITE, __NV_E4M3);
}
__device__ __forceinline__ void ldsm4(unsigned& r0, unsigned& r1, unsigned& r2, unsigned& r3, uint32_t addr) {
    asm volatile("ldmatrix.sync.aligned.m8n8.x4.shared.b16 {%0,%1,%2,%3}, [%4];"
        : "=r"(r0), "=r"(r1), "=r"(r2), "=r"(r3) : "r"(addr));
}
__device__ __forceinline__ void mma_e4m3(float* d, const unsigned* a, const unsigned* b) {
    asm volatile("mma.sync.aligned.m16n8k32.row.col.f32.e4m3.e4m3.f32 "
        "{%0,%1,%2,%3}, {%4,%5,%6,%7}, {%8,%9}, {%0,%1,%2,%3};"
        : "+f"(d[0]), "+f"(d[1]), "+f"(d[2]), "+f"(d[3])
        : "r"(a[0]), "r"(a[1]), "r"(a[2]), "r"(a[3]), "r"(b[0]), "r"(b[1]));
}

// ---------------- phase kernels ----------------
__global__ void absmax_both_kernel(const float* __restrict__ x, const float* __restrict__ w) {
    size_t tid0 = (size_t)blockIdx.x * blockDim.x + threadIdx.x;
    size_t stride = (size_t)gridDim.x * blockDim.x;
    const float4* p4 = (const float4*)x;
    unsigned m0 = 0;
    for (size_t i = tid0; i < (size_t)MM * KK / 4; i += stride) {
        float4 v = p4[i];
        unsigned a;
        a = __float_as_uint(v.x) & 0x7fffffffu; m0 = max(m0, a);
        a = __float_as_uint(v.y) & 0x7fffffffu; m0 = max(m0, a);
        a = __float_as_uint(v.z) & 0x7fffffffu; m0 = max(m0, a);
        a = __float_as_uint(v.w) & 0x7fffffffu; m0 = max(m0, a);
    }
    m0 = __reduce_max_sync(0xffffffffu, m0);
    if ((threadIdx.x & 31) == 0) atomicMax(&g_absmax[0], m0);

    const float4* q4 = (const float4*)w;
    unsigned m1 = 0;
    for (size_t i = tid0; i < (size_t)KK * NN / 4; i += stride) {
        float4 v = q4[i];
        unsigned a;
        a = __float_as_uint(v.x) & 0x7fffffffu; m1 = max(m1, a);
        a = __float_as_uint(v.y) & 0x7fffffffu; m1 = max(m1, a);
        a = __float_as_uint(v.z) & 0x7fffffffu; m1 = max(m1, a);
        a = __float_as_uint(v.w) & 0x7fffffffu; m1 = max(m1, a);
    }
    m1 = __reduce_max_sync(0xffffffffu, m1);
    if ((threadIdx.x & 31) == 0) atomicMax(&g_absmax[1], m1);
}

// Fused quantize: blocks [0, 16384) handle x (1 thread / 16B output chunk),
// blocks [16384, 17408) handle w (transpose via smem, one 128x128 tile each).
#define QX_BLOCKS ((MM / 16) * KK / 256)   // 16384
__global__ void quantize_fused_kernel(const float* __restrict__ x, const float* __restrict__ w) {
    __shared__ unsigned char sm[128 * 132];
    unsigned bid = blockIdx.x, t = threadIdx.x;
    if (bid < QX_BLOCKS) {
        // ---- x path: [M,K] fp32 -> g_xq tiled (mtile,ktile) 128x128B SW128 ----
        float sx = 448.0f / __uint_as_float(g_absmax[0]);
        unsigned idx = bid * 256 + t;     // [0, M*K/16)
        unsigned row = idx >> 8;          // K/16 = 256 chunks per row
        unsigned kc  = idx & 255;
        unsigned ktile = kc >> 3, c16 = kc & 7;
        const float4* src = (const float4*)(x + (size_t)row * KK + ktile * 128 + c16 * 16);
        unsigned out[4];
#pragma unroll
        for (int i = 0; i < 4; i++) {
            float4 v = src[i];
            unsigned b0 = q_e4m3(v.x * sx), b1 = q_e4m3(v.y * sx);
            unsigned b2 = q_e4m3(v.z * sx), b3 = q_e4m3(v.w * sx);
            out[i] = b0 | (b1 << 8) | (b2 << 16) | (b3 << 24);
        }
        unsigned tile = (row >> 7) * KTILES + ktile;
        unsigned r = row & 127;
        *(uint4*)(g_xq + (size_t)tile * TILE_BYTES + swz128(r * 128 + c16 * 16)) =
            make_uint4(out[0], out[1], out[2], out[3]);
    } else {
        // ---- w path: [K,N] fp32 -> transpose+quantize -> g_wq tiled SW128 ----
        unsigned bid2 = bid - QX_BLOCKS;            // [0, 1024)
        float swc = 448.0f / __uint_as_float(g_absmax[1]);
        unsigned ntile = bid2 >> 5, ktile = bid2 & 31;
#pragma unroll 4
        for (int i = 0; i < 16; i++) {
            unsigned f = t + i * 256;        // [0, 4096) float4 slots
            unsigned kk = f >> 5, n4 = f & 31;
            float4 v = *(const float4*)(w + (size_t)(ktile * 128 + kk) * NN + ntile * 128 + n4 * 4);
            unsigned nn = n4 * 4;
            sm[(nn + 0) * 132 + kk] = q_e4m3(v.x * swc);
            sm[(nn + 1) * 132 + kk] = q_e4m3(v.y * swc);
            sm[(nn + 2) * 132 + kk] = q_e4m3(v.z * swc);
            sm[(nn + 3) * 132 + kk] = q_e4m3(v.w * swc);
        }
        __syncthreads();
        size_t tbase = (size_t)(ntile * KTILES + ktile) * TILE_BYTES;
#pragma unroll
        for (int i = 0; i < 4; i++) {
            unsigned c = t + i * 256;        // [0, 1024) 16B chunks
            unsigned r = c >> 3, c16 = c & 7;
            unsigned base = r * 132 + c16 * 16;
            unsigned o0 = *(const unsigned*)(sm + base + 0);
            unsigned o1 = *(const unsigned*)(sm + base + 4);
            unsigned o2 = *(const unsigned*)(sm + base + 8);
            unsigned o3 = *(const unsigned*)(sm + base + 12);
            *(uint4*)(g_wq + tbase + swz128(r * 128 + c16 * 16)) = make_uint4(o0, o1, o2, o3);
        }
    }
}

// ---------------- GEMM (R6-proven shape) ----------------
// 4096 CTAs (128x128 tiles), 288 threads: 8 compute warps (2 M x 4 N grid of
// 64x32 warp tiles, ~130 regs -> NO spill) + 1 producer warp. 4-stage
// cp.async.bulk pipeline over pre-tiled SW128 tiles.
__global__ void __launch_bounds__(NTG, 1) gemm_kernel(float* __restrict__ out) {
    extern __shared__ char dsm[];
    __shared__ __align__(8) unsigned long long bars[2 * STAGES]; // full[s], consumed[s]

    unsigned tid = threadIdx.x, wid = tid >> 5, lane = tid & 31;
    unsigned tile_base = (smem_u32(dsm) + 1023u) & ~1023u;
    unsigned bars_a = smem_u32(bars);
    unsigned mtile = blockIdx.x >> 5, ntile = blockIdx.x & 31;

    const unsigned char* Ag = g_xq + (size_t)mtile * KTILES * TILE_BYTES;
    const unsigned char* Bg = g_wq + (size_t)ntile * KTILES * TILE_BYTES;

    if (tid == 0) {
#pragma unroll
        for (int s = 0; s < STAGES; s++) {
            MBARRIER_INIT(bars_a + 8 * s, 1);              // full[s] (tx-based)
            MBARRIER_INIT(bars_a + 8 * (STAGES + s), 8);   // consumed[s] (8 warps)
        }
    }
    __syncthreads();

    if (wid == 8) {
        // producer warp
        if (elect_one_pred()) {
            for (int kt = 0; kt < KTILES; kt++) {
                int s = kt % STAGES, u = kt / STAGES;
                if (u > 0) MBARRIER_WAIT_PARITY_RELAXED(bars_a + 8 * (STAGES + s), (u - 1) & 1);
                uint32_t full = bars_a + 8 * s;
                MBARRIER_EXPECT_TX(full, (uint32_t)STAGE_BYTES);
                uint32_t dst = tile_base + (unsigned)s * (unsigned)STAGE_BYTES;
                bulk_g2s(dst,              Ag + (size_t)kt * TILE_BYTES, TILE_BYTES, full);
                bulk_g2s(dst + TILE_BYTES, Bg + (size_t)kt * TILE_BYTES, TILE_BYTES, full);
            }
        }
    } else {
        // 8 compute warps: 2(M) x 4(N); each computes 64x32 of the 128x128 tile
        unsigned wm = wid >> 2, wn = wid & 3;
        float d[4][4][4];
#pragma unroll
        for (int i = 0; i < 4; i++)
#pragma unroll
            for (int j = 0; j < 4; j++)
#pragma unroll
                for (int k = 0; k < 4; k++) d[i][j][k] = 0.0f;

        // per-lane ldmatrix addressing into SW128-swizzled 128x128B tiles
        unsigned xorm = (lane & 7) << 4;
        unsigned aRow[4], bRow[2];
#pragma unroll
        for (int am = 0; am < 4; am++)
            aRow[am] = (wm * 64 + am * 16 + ((lane >> 3) & 1) * 8 + (lane & 7)) * 128;
#pragma unroll
        for (int p = 0; p < 2; p++)
            bRow[p] = (wn * 32 + p * 16 + (lane >> 4) * 8 + (lane & 7)) * 128;
        unsigned aColBase = (lane >> 4) << 4;         // 0 or 16
        unsigned bColBase = ((lane >> 3) & 1) << 4;   // 0 or 16

        for (int kt = 0; kt < KTILES; kt++) {
            int s = kt % STAGES, u = kt / STAGES;
            MBARRIER_WAIT_PARITY(bars_a + 8 * s, u & 1);
            uint32_t sA = tile_base + (unsigned)s * (unsigned)STAGE_BYTES;
            uint32_t sB = sA + TILE_BYTES;
#pragma unroll
            for (int kk = 0; kk < 4; kk++) {
                unsigned acol = ((unsigned)(kk * 32) + aColBase) ^ xorm;
                unsigned bcol = ((unsigned)(kk * 32) + bColBase) ^ xorm;
                unsigned a[4][4];
#pragma unroll
                for (int am = 0; am < 4; am++)
                    ldsm4(a[am][0], a[am][1], a[am][2], a[am][3], sA + aRow[am] + acol);
                unsigned b[4][2];
#pragma unroll
                for (int p = 0; p < 2; p++)
                    ldsm4(b[2 * p][0], b[2 * p][1], b[2 * p + 1][0], b[2 * p + 1][1],
                          sB + bRow[p] + bcol);
#pragma unroll
                for (int am = 0; am < 4; am++)
#pragma unroll
                    for (int bn = 0; bn < 4; bn++)
                        mma_e4m3(d[am][bn], a[am], b[bn]);
            }
            __syncwarp();
            if (lane == 0) MBARRIER_ARRIVE(bars_a + 8 * (STAGES + s));
        }

        // epilogue: inv = 1/(sx*sw)
        float sx = 448.0f / __uint_as_float(g_absmax[0]);
        float sw = 448.0f / __uint_as_float(g_absmax[1]);
        float inv = 1.0f / (sx * sw);
        unsigned gID = lane >> 2, tID = lane & 3;
        unsigned colBase = ntile * 128 + wn * 32 + tID * 2;
#pragma unroll
        for (int am = 0; am < 4; am++) {
            unsigned row0 = mtile * 128 + wm * 64 + am * 16 + gID;
            float* op0 = out + (size_t)row0 * NN + colBase;
            float* op1 = op0 + (size_t)8 * NN;
#pragma unroll
            for (int bn = 0; bn < 4; bn++) {
                float2 v0 = make_float2(d[am][bn][0] * inv, d[am][bn][1] * inv);
                float2 v1 = make_float2(d[am][bn][2] * inv, d[am][bn][3] * inv);
                *(float2*)(op0 + bn * 8) = v0;
                *(float2*)(op1 + bn * 8) = v1;
            }
        }
    }
}

// ---------------- launch ----------------
extern "C" void kernel_launch(void* const* d_in, const int* in_sizes, int n_in,
                              void* d_out, int out_size) {
    (void)in_sizes; (void)n_in; (void)out_size;
    const float* x = (const float*)d_in[0];
    const float* w = (const float*)d_in[1];
    float* out = (float*)d_out;

    cudaFuncSetAttribute(gemm_kernel, cudaFuncAttributeMaxDynamicSharedMemorySize, SMEM_DYN);

    absmax_both_kernel<<<2048, 256>>>(x, w);
    quantize_fused_kernel<<<QX_BLOCKS + NTILES * KTILES, 256>>>(x, w);
    gemm_kernel<<<MTILES * NTILES, NTG, SMEM_DYN>>>(out);
}

// round 15
// speedup vs baseline: 1.1300x; 1.1300x over previous
#include <cuda_runtime.h>
#include <cuda_fp8.h>
#include <cstdint>
#include <cstddef>

#define MM 16384
#define KK 4096
#define NN 4096
#define KTILES (KK/128)   // 32
#define NTILES (NN/128)   // 32
#define MTILES (MM/128)   // 128
#define TILE_BYTES 16384
#define STAGES 3
#define STAGE_BYTES (2*TILE_BYTES)            // A(16KB) + B(16KB)
#define SMEM_DYN (1024 + STAGES*STAGE_BYTES)  // 99328 B -> TWO CTAs/SM (198KB<228KB)
#define NTG 288           // 8 compute warps (64x32 tiles) + 1 producer warp

// Evidence log: plain compute_103 device pass (R2) -> mma.sync fp8 path runs.
// R6 = 406us total (gemm ~270) with: 64x32 warp tiles (~112 regs), STAGES=3
// (99KB smem), launch_bounds(288) no-minBlocks -> OCCUPANCY 2. R14 proved the
// regression driver: identical GEMM at STAGES=4 (132KB, occ 1) ran 5.5x slower.
// Law: need no-spill regs <=112 AND smem <=114KB for occ 2. This round restores
// the exact R6 GEMM config + keeps 3-launch consolidated phases.

// ---------------- scratch (device globals: allocation-free) ----------------
__device__ __align__(1024) unsigned char g_xq[(size_t)MM*KK]; // 64 MB, tiled+swizzled
__device__ __align__(1024) unsigned char g_wq[(size_t)NN*KK]; // 16 MB, tiled+swizzled
__device__ unsigned g_absmax[2];  // zero-init; atomicMax idempotent across replays

// ---------------- PTX helpers ----------------
__device__ __forceinline__ uint32_t smem_u32(const void* p) {
    uint32_t a;
    asm("{ .reg .u64 t; cvta.to.shared.u64 t, %1; cvt.u32.u64 %0, t; }" : "=r"(a) : "l"(p));
    return a;
}
__device__ __forceinline__ uint32_t elect_one_pred() {
    uint32_t p;
    asm volatile("{ .reg .pred p; elect.sync _|p, 0xFFFFFFFF; selp.b32 %0, 1, 0, p; }" : "=r"(p));
    return p;
}
#define MBARRIER_INIT(addr, cnt) \
    asm volatile("mbarrier.init.shared.b64 [%0], %1;" :: "r"(addr), "r"(cnt) : "memory")
#define MBARRIER_EXPECT_TX(addr, bytes) \
    asm volatile("mbarrier.arrive.expect_tx.shared.b64 _, [%0], %1;" :: "r"(addr), "r"(bytes) : "memory")
#define MBARRIER_ARRIVE(addr) \
    asm volatile("mbarrier.arrive.shared.b64 _, [%0];" :: "r"(addr) : "memory")
#define MBARRIER_WAIT_PARITY(mbar_smem_addr, phase_parity) do { \
    uint32_t _mbar = (uint32_t)(mbar_smem_addr); \
    uint32_t _parity = (uint32_t)(phase_parity); \
    uint32_t _done; \
    asm volatile("{ .reg .pred p; mbarrier.try_wait.parity.acquire.cta.shared::cta.b64 p, [%1], %2; selp.b32 %0, 1, 0, p; }" \
        : "=r"(_done) : "r"(_mbar), "r"(_parity) : "memory"); \
    if (!_done) { \
        asm volatile("{ .reg .pred P1; WAIT_LOOP_%=: mbarrier.try_wait.parity.acquire.cta.shared::cta.b64 P1, [%0], %1, 0x989680; @P1 bra.uni WAIT_DONE_%=; bra.uni WAIT_LOOP_%=; WAIT_DONE_%=: }" \
            :: "r"(_mbar), "r"(_parity) : "memory"); \
    } \
} while(0)
#define MBARRIER_WAIT_PARITY_RELAXED(mbar_smem_addr, phase_parity) do { \
    uint32_t _mbar = (uint32_t)(mbar_smem_addr); \
    uint32_t _parity = (uint32_t)(phase_parity); \
    uint32_t _done; \
    asm volatile("{ .reg .pred p; mbarrier.try_wait.parity.relaxed.cta.shared::cta.b64 p, [%1], %2, 0x989680; selp.b32 %0, 1, 0, p; }" \
        : "=r"(_done) : "r"(_mbar), "r"(_parity) : "memory"); \
    if (!_done) { \
        asm volatile("{ .reg .pred P1; WAIT_LOOP_%=: mbarrier.try_wait.parity.relaxed.cta.shared::cta.b64 P1, [%0], %1, 0x989680; @P1 bra.uni WAIT_DONE_%=; bra.uni WAIT_LOOP_%=; WAIT_DONE_%=: }" \
            :: "r"(_mbar), "r"(_parity) : "memory"); \
    } \
} while(0)

__device__ __forceinline__ void bulk_g2s(uint32_t dst, const void* src, uint32_t bytes, uint32_t mbar) {
    asm volatile(
        "cp.async.bulk.shared::cluster.global.mbarrier::complete_tx::bytes [%0], [%1], %2, [%3];"
        :: "r"(dst), "l"(src), "r"(bytes), "r"(mbar) : "memory");
}

__device__ __forceinline__ unsigned swz128(unsigned off) { return off ^ ((off >> 3) & 0x70); }
__device__ __forceinline__ unsigned char q_e4m3(float v) {
    return (unsigned char)__nv_cvt_float_to_fp8(v, __NV_SATFINITE, __NV_E4M3);
}
__device__ __forceinline__ void ldsm4(unsigned& r0, unsigned& r1, unsigned& r2, unsigned& r3, uint32_t addr) {
    asm volatile("ldmatrix.sync.aligned.m8n8.x4.shared.b16 {%0,%1,%2,%3}, [%4];"
        : "=r"(r0), "=r"(r1), "=r"(r2), "=r"(r3) : "r"(addr));
}
__device__ __forceinline__ void mma_e4m3(float* d, const unsigned* a, const unsigned* b) {
    asm volatile("mma.sync.aligned.m16n8k32.row.col.f32.e4m3.e4m3.f32 "
        "{%0,%1,%2,%3}, {%4,%5,%6,%7}, {%8,%9}, {%0,%1,%2,%3};"
        : "+f"(d[0]), "+f"(d[1]), "+f"(d[2]), "+f"(d[3])
        : "r"(a[0]), "r"(a[1]), "r"(a[2]), "r"(a[3]), "r"(b[0]), "r"(b[1]));
}

// ---------------- phase kernels ----------------
__global__ void absmax_both_kernel(const float* __restrict__ x, const float* __restrict__ w) {
    size_t tid0 = (size_t)blockIdx.x * blockDim.x + threadIdx.x;
    size_t stride = (size_t)gridDim.x * blockDim.x;
    const float4* p4 = (const float4*)x;
    unsigned m0 = 0;
    for (size_t i = tid0; i < (size_t)MM * KK / 4; i += stride) {
        float4 v = p4[i];
        unsigned a;
        a = __float_as_uint(v.x) & 0x7fffffffu; m0 = max(m0, a);
        a = __float_as_uint(v.y) & 0x7fffffffu; m0 = max(m0, a);
        a = __float_as_uint(v.z) & 0x7fffffffu; m0 = max(m0, a);
        a = __float_as_uint(v.w) & 0x7fffffffu; m0 = max(m0, a);
    }
    m0 = __reduce_max_sync(0xffffffffu, m0);
    if ((threadIdx.x & 31) == 0) atomicMax(&g_absmax[0], m0);

    const float4* q4 = (const float4*)w;
    unsigned m1 = 0;
    for (size_t i = tid0; i < (size_t)KK * NN / 4; i += stride) {
        float4 v = q4[i];
        unsigned a;
        a = __float_as_uint(v.x) & 0x7fffffffu; m1 = max(m1, a);
        a = __float_as_uint(v.y) & 0x7fffffffu; m1 = max(m1, a);
        a = __float_as_uint(v.z) & 0x7fffffffu; m1 = max(m1, a);
        a = __float_as_uint(v.w) & 0x7fffffffu; m1 = max(m1, a);
    }
    m1 = __reduce_max_sync(0xffffffffu, m1);
    if ((threadIdx.x & 31) == 0) atomicMax(&g_absmax[1], m1);
}

// Fused quantize: blocks [0, 16384) handle x (1 thread / 16B output chunk),
// blocks [16384, 17408) handle w (transpose via smem, one 128x128 tile each).
#define QX_BLOCKS ((MM / 16) * KK / 256)   // 16384
__global__ void quantize_fused_kernel(const float* __restrict__ x, const float* __restrict__ w) {
    __shared__ unsigned char sm[128 * 132];
    unsigned bid = blockIdx.x, t = threadIdx.x;
    if (bid < QX_BLOCKS) {
        // ---- x path: [M,K] fp32 -> g_xq tiled (mtile,ktile) 128x128B SW128 ----
        float sx = 448.0f / __uint_as_float(g_absmax[0]);
        unsigned idx = bid * 256 + t;     // [0, M*K/16)
        unsigned row = idx >> 8;          // K/16 = 256 chunks per row
        unsigned kc  = idx & 255;
        unsigned ktile = kc >> 3, c16 = kc & 7;
        const float4* src = (const float4*)(x + (size_t)row * KK + ktile * 128 + c16 * 16);
        unsigned out[4];
#pragma unroll
        for (int i = 0; i < 4; i++) {
            float4 v = src[i];
            unsigned b0 = q_e4m3(v.x * sx), b1 = q_e4m3(v.y * sx);
            unsigned b2 = q_e4m3(v.z * sx), b3 = q_e4m3(v.w * sx);
            out[i] = b0 | (b1 << 8) | (b2 << 16) | (b3 << 24);
        }
        unsigned tile = (row >> 7) * KTILES + ktile;
        unsigned r = row & 127;
        *(uint4*)(g_xq + (size_t)tile * TILE_BYTES + swz128(r * 128 + c16 * 16)) =
            make_uint4(out[0], out[1], out[2], out[3]);
    } else {
        // ---- w path: [K,N] fp32 -> transpose+quantize -> g_wq tiled SW128 ----
        unsigned bid2 = bid - QX_BLOCKS;            // [0, 1024)
        float swc = 448.0f / __uint_as_float(g_absmax[1]);
        unsigned ntile = bid2 >> 5, ktile = bid2 & 31;
#pragma unroll 4
        for (int i = 0; i < 16; i++) {
            unsigned f = t + i * 256;        // [0, 4096) float4 slots
            unsigned kk = f >> 5, n4 = f & 31;
            float4 v = *(const float4*)(w + (size_t)(ktile * 128 + kk) * NN + ntile * 128 + n4 * 4);
            unsigned nn = n4 * 4;
            sm[(nn + 0) * 132 + kk] = q_e4m3(v.x * swc);
            sm[(nn + 1) * 132 + kk] = q_e4m3(v.y * swc);
            sm[(nn + 2) * 132 + kk] = q_e4m3(v.z * swc);
            sm[(nn + 3) * 132 + kk] = q_e4m3(v.w * swc);
        }
        __syncthreads();
        size_t tbase = (size_t)(ntile * KTILES + ktile) * TILE_BYTES;
#pragma unroll
        for (int i = 0; i < 4; i++) {
            unsigned c = t + i * 256;        // [0, 1024) 16B chunks
            unsigned r = c >> 3, c16 = c & 7;
            unsigned base = r * 132 + c16 * 16;
            unsigned o0 = *(const unsigned*)(sm + base + 0);
            unsigned o1 = *(const unsigned*)(sm + base + 4);
            unsigned o2 = *(const unsigned*)(sm + base + 8);
            unsigned o3 = *(const unsigned*)(sm + base + 12);
            *(uint4*)(g_wq + tbase + swz128(r * 128 + c16 * 16)) = make_uint4(o0, o1, o2, o3);
        }
    }
}

// ---------------- GEMM (exact R6 config: occ 2) ----------------
// 4096 CTAs (128x128 tiles), 288 threads: 8 compute warps (2 M x 4 N grid of
// 64x32 warp tiles, ~112 regs) + 1 producer warp. 3-stage cp.async.bulk
// pipeline, 99KB smem -> 2 CTAs/SM. NO minBlocks in launch_bounds (R6 exact).
__global__ void __launch_bounds__(NTG) gemm_kernel(float* __restrict__ out) {
    extern __shared__ char dsm[];
    __shared__ __align__(8) unsigned long long bars[2 * STAGES]; // full[s], consumed[s]

    unsigned tid = threadIdx.x, wid = tid >> 5, lane = tid & 31;
    unsigned tile_base = (smem_u32(dsm) + 1023u) & ~1023u;
    unsigned bars_a = smem_u32(bars);
    unsigned mtile = blockIdx.x >> 5, ntile = blockIdx.x & 31;

    const unsigned char* Ag = g_xq + (size_t)mtile * KTILES * TILE_BYTES;
    const unsigned char* Bg = g_wq + (size_t)ntile * KTILES * TILE_BYTES;

    if (tid == 0) {
#pragma unroll
        for (int s = 0; s < STAGES; s++) {
            MBARRIER_INIT(bars_a + 8 * s, 1);              // full[s] (tx-based)
            MBARRIER_INIT(bars_a + 8 * (STAGES + s), 8);   // consumed[s] (8 warps)
        }
    }
    __syncthreads();

    if (wid == 8) {
        // producer warp
        if (elect_one_pred()) {
            for (int kt = 0; kt < KTILES; kt++) {
                int s = kt % STAGES, u = kt / STAGES;
                if (u > 0) MBARRIER_WAIT_PARITY_RELAXED(bars_a + 8 * (STAGES + s), (u - 1) & 1);
                uint32_t full = bars_a + 8 * s;
                MBARRIER_EXPECT_TX(full, (uint32_t)STAGE_BYTES);
                uint32_t dst = tile_base + (unsigned)s * (unsigned)STAGE_BYTES;
                bulk_g2s(dst,              Ag + (size_t)kt * TILE_BYTES, TILE_BYTES, full);
                bulk_g2s(dst + TILE_BYTES, Bg + (size_t)kt * TILE_BYTES, TILE_BYTES, full);
            }
        }
    } else {
        // 8 compute warps: 2(M) x 4(N); each computes 64x32 of the 128x128 tile
        unsigned wm = wid >> 2, wn = wid & 3;
        float d[4][4][4];
#pragma unroll
        for (int i = 0; i < 4; i++)
#pragma unroll
            for (int j = 0; j < 4; j++)
#pragma unroll
                for (int k = 0; k < 4; k++) d[i][j][k] = 0.0f;

        // per-lane ldmatrix addressing into SW128-swizzled 128x128B tiles
        unsigned xorm = (lane & 7) << 4;
        unsigned aRow[4], bRow[2];
#pragma unroll
        for (int am = 0; am < 4; am++)
            aRow[am] = (wm * 64 + am * 16 + ((lane >> 3) & 1) * 8 + (lane & 7)) * 128;
#pragma unroll
        for (int p = 0; p < 2; p++)
            bRow[p] = (wn * 32 + p * 16 + (lane >> 4) * 8 + (lane & 7)) * 128;
        unsigned aColBase = (lane >> 4) << 4;         // 0 or 16
        unsigned bColBase = ((lane >> 3) & 1) << 4;   // 0 or 16

        for (int kt = 0; kt < KTILES; kt++) {
            int s = kt % STAGES, u = kt / STAGES;
            MBARRIER_WAIT_PARITY(bars_a + 8 * s, u & 1);
            uint32_t sA = tile_base + (unsigned)s * (unsigned)STAGE_BYTES;
            uint32_t sB = sA + TILE_BYTES;
#pragma unroll
            for (int kk = 0; kk < 4; kk++) {
                unsigned acol = ((unsigned)(kk * 32) + aColBase) ^ xorm;
                unsigned bcol = ((unsigned)(kk * 32) + bColBase) ^ xorm;
                unsigned a[4][4];
#pragma unroll
                for (int am = 0; am < 4; am++)
                    ldsm4(a[am][0], a[am][1], a[am][2], a[am][3], sA + aRow[am] + acol);
                unsigned b[4][2];
#pragma unroll
                for (int p = 0; p < 2; p++)
                    ldsm4(b[2 * p][0], b[2 * p][1], b[2 * p + 1][0], b[2 * p + 1][1],
                          sB + bRow[p] + bcol);
#pragma unroll
                for (int am = 0; am < 4; am++)
#pragma unroll
                    for (int bn = 0; bn < 4; bn++)
                        mma_e4m3(d[am][bn], a[am], b[bn]);
            }
            __syncwarp();
            if (lane == 0) MBARRIER_ARRIVE(bars_a + 8 * (STAGES + s));
        }

        // epilogue: inv = 1/(sx*sw)
        float sx = 448.0f / __uint_as_float(g_absmax[0]);
        float sw = 448.0f / __uint_as_float(g_absmax[1]);
        float inv = 1.0f / (sx * sw);
        unsigned gID = lane >> 2, tID = lane & 3;
        unsigned colBase = ntile * 128 + wn * 32 + tID * 2;
#pragma unroll
        for (int am = 0; am < 4; am++) {
            unsigned row0 = mtile * 128 + wm * 64 + am * 16 + gID;
            float* op0 = out + (size_t)row0 * NN + colBase;
            float* op1 = op0 + (size_t)8 * NN;
#pragma unroll
            for (int bn = 0; bn < 4; bn++) {
                float2 v0 = make_float2(d[am][bn][0] * inv, d[am][bn][1] * inv);
                float2 v1 = make_float2(d[am][bn][2] * inv, d[am][bn][3] * inv);
                *(float2*)(op0 + bn * 8) = v0;
                *(float2*)(op1 + bn * 8) = v1;
            }
        }
    }
}

// ---------------- launch ----------------
extern "C" void kernel_launch(void* const* d_in, const int* in_sizes, int n_in,
                              void* d_out, int out_size) {
    (void)in_sizes; (void)n_in; (void)out_size;
    const float* x = (const float*)d_in[0];
    const float* w = (const float*)d_in[1];
    float* out = (float*)d_out;

    cudaFuncSetAttribute(gemm_kernel, cudaFuncAttributeMaxDynamicSharedMemorySize, SMEM_DYN);

    absmax_both_kernel<<<2048, 256>>>(x, w);
    quantize_fused_kernel<<<QX_BLOCKS + NTILES * KTILES, 256>>>(x, w);
    gemm_kernel<<<MTILES * NTILES, NTG, SMEM_DYN>>>(out);
}